// round 16
// baseline (speedup 1.0000x reference)
#include <cuda_runtime.h>
#include <cstdint>

// CondConv3d via tf32 mma.sync implicit GEMM (tensor pipe; compute_103-safe).
// Round 16: R14 pipeline (12 stages = 3dz x 4kc, double-buffered), with:
//  - B fragments pair-packed in prep so each (tap,ni) is ONE LDS.64
//    (4 loads/unit instead of 8; banks 8g+2tig conflict-free per phase)
//  - halo select compile-time-limited to (kw==0, mi==0)
//  - smem 61.9KB/CTA, 2 CTAs/SM
//
// out[b] = s[b] * (conv3d(x[b], Wsum) + bias_sum)

#define B_ 8
#define CIN 32
#define COUT 32
#define DD 16
#define HH_ 64
#define WW 64

#define TH 8                        // output h rows per block
#define XROWS (TH + 2)              // 10
#define ROW_PITCH 68                // 64 data + 2 zero + 2 pad
#define CQ_PITCH (XROWS * ROW_PITCH)   // 680 floats per channel
#define XQ_FLOATS (8 * CQ_PITCH)    // 5440 floats per xT quarter (8 c)
// W slice (one dz,kc): float2-packed [t9][ni][g][tig] -> 9*4*8*4 = 1152 float2
#define W_SLICE 2304                // floats
#define W_FLOATS (12 * W_SLICE)     // 27648 (gmem, [dz][kc] slices)
#define OFF_XT 0
#define OFF_W (2 * XQ_FLOATS)       // 10880
#define SMEM_FLOATS (2 * XQ_FLOATS + 2 * W_SLICE)  // 15488 floats = 61952 B

__device__ float g_wt[W_FLOATS];
__device__ float g_bias[COUT];
__device__ float g_s[B_];

__device__ __forceinline__ float to_tf32(float v) {
    uint32_t u;
    asm("cvt.rna.tf32.f32 %0, %1;" : "=r"(u) : "f"(v));
    return __uint_as_float(u);
}

__global__ void prep_kernel(const float* __restrict__ weight,
                            const float* __restrict__ bias,
                            const float* __restrict__ rw) {
    int idx = blockIdx.x * 256 + threadIdx.x;
    if (idx < W_FLOATS) {
        // slice s = dz*4+kc; within slice: float idx =
        //   ((t9*4 + ni)*8 + g)*8 + tig*2 + half
        int s   = idx / W_SLICE;
        int r   = idx % W_SLICE;
        int dz  = s >> 2;
        int kc  = s & 3;
        int t9  = r >> 8;            // 256 floats per t9
        int r2  = r & 255;
        int ni  = r2 >> 6;
        int r3  = r2 & 63;
        int g2  = r3 >> 3;
        int r4  = r3 & 7;
        int tig = r4 >> 1;
        int half = r4 & 1;
        int o = ni * 8 + g2;
        int c = kc * 8 + tig + 4 * half;
        int tap = dz * 9 + t9;
        float v = 0.f;
        #pragma unroll
        for (int e = 0; e < 8; e++)
            v += weight[((e * 32 + o) * 32 + c) * 27 + tap];
        g_wt[idx] = to_tf32(v);
    }
    if (blockIdx.x == 0) {
        int tid = threadIdx.x;
        if (tid < COUT) {
            float sv = 0.f;
            #pragma unroll
            for (int e = 0; e < 8; e++) sv += bias[e * COUT + tid];
            g_bias[tid] = sv;
        } else if (tid < COUT + B_) {
            int b = tid - COUT;
            float sv = 0.f;
            #pragma unroll
            for (int e = 0; e < 8; e++) sv += rw[b * 8 + e];
            g_s[b] = sv;
        }
    }
}

// ---- cp.async helpers ----
__device__ __forceinline__ void cp16_zfill(uint32_t saddr, const float* g, int srcsz) {
    asm volatile("cp.async.cg.shared.global [%0], [%1], 16, %2;"
                 :: "r"(saddr), "l"(g), "r"(srcsz));
}
__device__ __forceinline__ void cp16(uint32_t saddr, const float* g) {
    asm volatile("cp.async.cg.shared.global [%0], [%1], 16;"
                 :: "r"(saddr), "l"(g));
}
__device__ __forceinline__ void cp_commit() { asm volatile("cp.async.commit_group;"); }
__device__ __forceinline__ void cp_wait1()  { asm volatile("cp.async.wait_group 1;"); }
__device__ __forceinline__ void cp_wait0()  { asm volatile("cp.async.wait_group 0;"); }

__device__ __forceinline__ void mma_tf32(float* c, uint32_t a0, uint32_t a1,
                                         uint32_t a2, uint32_t a3,
                                         uint32_t b0, uint32_t b1) {
    asm volatile("mma.sync.aligned.m16n8k8.row.col.f32.tf32.tf32.f32 "
                 "{%0,%1,%2,%3}, {%4,%5,%6,%7}, {%8,%9}, {%0,%1,%2,%3};"
                 : "+f"(c[0]), "+f"(c[1]), "+f"(c[2]), "+f"(c[3])
                 : "r"(a0), "r"(a1), "r"(a2), "r"(a3), "r"(b0), "r"(b1));
}

extern __shared__ float smem[];

__global__ __launch_bounds__(256, 2) void conv_kernel(const float* __restrict__ x,
                                                      float* __restrict__ out) {
    const int tid  = threadIdx.x;
    const int wid  = tid >> 5;         // warp = one output h row (0..7)
    const int lane = tid & 31;
    const int g    = lane >> 2;        // fragment groupID
    const int tig  = lane & 3;         // fragment threadID-in-group

    const int htile = blockIdx.x;      // 8 h rows each
    const int d     = blockIdx.y;
    const int b     = blockIdx.z;
    const int h0    = htile * TH;

    const float* __restrict__ xb = x + (size_t)b * CIN * DD * HH_ * WW;
    const uint32_t smem_u = (uint32_t)__cvta_generic_to_shared(smem);

    // ---- init permanent zero slots (cols 64..67) in both xT buffers ----
    for (int i = tid; i < 2 * 8 * XROWS * 4; i += 256) {
        int bf  = i / (8 * XROWS * 4);
        int rem = i % (8 * XROWS * 4);
        int cl  = rem / (XROWS * 4);
        int r   = (rem / 4) % XROWS;
        int z   = rem & 3;
        smem[OFF_XT + bf * XQ_FLOATS + cl * CQ_PITCH + r * ROW_PITCH + 64 + z] = 0.f;
    }

    // ---- stage one (dz,kc) xT quarter: 8c x 10 rows x 16 chunks ----
    const int sc  = tid >> 5;          // c-local 0..7 (warp per channel)
    const int s32 = tid & 31;
    auto stage_xq = [&](int s, int bf) {
        int dz = s >> 2, kc = s & 3;
        int gd = d + dz - 1;
        bool dok = (gd >= 0) && (gd < DD);
        const float* base =
            xb + ((size_t)(kc * 8 + sc) * DD + (dok ? gd : 0)) * HH_ * WW;
        uint32_t dst0 = smem_u + (OFF_XT + bf * XQ_FLOATS + sc * CQ_PITCH) * 4;
        #pragma unroll
        for (int j = 0; j < 5; j++) {
            int slot = s32 + 32 * j;   // 0..159
            int row  = slot >> 4;      // 0..9
            int q    = slot & 15;
            int gh = h0 + row - 1;
            bool ok = dok && (gh >= 0) && (gh < HH_);
            cp16_zfill(dst0 + (row * ROW_PITCH + q * 4) * 4,
                       base + (ok ? gh : 0) * WW + q * 4, ok ? 16 : 0);
        }
    };
    // ---- stage one (dz,kc) W slice: 576 float4 ----
    auto stage_w = [&](int s, int bf) {
        const float* src = g_wt + s * W_SLICE;
        uint32_t dst = smem_u + (OFF_W + bf * W_SLICE) * 4;
        #pragma unroll
        for (int k = 0; k < 3; k++) {
            int idx = tid + 256 * k;
            if (idx < W_SLICE / 4)
                cp16(dst + idx * 16, src + idx * 4);
        }
    };

    // ---- accumulators: C[mi][ni][4] (M64 x N32 per warp) ----
    float acc[4][4][4];
    #pragma unroll
    for (int mi = 0; mi < 4; mi++)
        #pragma unroll
        for (int ni = 0; ni < 4; ni++)
            #pragma unroll
            for (int r = 0; r < 4; r++) acc[mi][ni][r] = 0.f;

    // ---- prologue ----
    stage_xq(0, 0); stage_w(0, 0); cp_commit();
    stage_xq(1, 1); stage_w(1, 1); cp_commit();
    cp_wait1();
    __syncthreads();

    #pragma unroll 1
    for (int s = 0; s < 12; s++) {
        const int bf = s & 1;
        const uint32_t* xbuf = reinterpret_cast<const uint32_t*>(
            smem + OFF_XT + bf * XQ_FLOATS);
        // per-lane W pointer: float2 index g*4 + tig within slice
        const float2* wlane = reinterpret_cast<const float2*>(
            smem + OFF_W + bf * W_SLICE) + g * 4 + tig;

        // ---- compute stage s: 9 taps x 16 MMAs ----
        #pragma unroll
        for (int kh = 0; kh < 3; kh++) {
            const uint32_t* xrow = xbuf + (wid + kh) * ROW_PITCH + tig * CQ_PITCH;
            #pragma unroll
            for (int kw = 0; kw < 3; kw++) {
                const int kwm1 = kw - 1;
                const float2* wt = wlane + (kh * 3 + kw) * 128;
                // B fragments: 4x LDS.64 (pair-packed)
                uint32_t b0[4], b1[4];
                #pragma unroll
                for (int ni = 0; ni < 4; ni++) {
                    float2 bb = wt[ni * 32];
                    b0[ni] = __float_as_uint(bb.x);
                    b1[ni] = __float_as_uint(bb.y);
                }
                #pragma unroll
                for (int mi = 0; mi < 4; mi++) {
                    const int win = mi * 16 + g + kwm1;
                    // halo select only live for kw==0, mi==0 (win = g-1)
                    const int r0 = (kw == 0 && mi == 0) ? ((win < 0) ? 65 : win)
                                                        : win;
                    const int r1 = win + 8;            // max 64 -> zero slot
                    uint32_t a0 = xrow[r0];
                    uint32_t a1 = xrow[r1];
                    uint32_t a2 = xrow[r0 + 4 * CQ_PITCH];
                    uint32_t a3 = xrow[r1 + 4 * CQ_PITCH];
                    #pragma unroll
                    for (int ni = 0; ni < 4; ni++)
                        mma_tf32(acc[mi][ni], a0, a1, a2, a3, b0[ni], b1[ni]);
                }
            }
        }

        // ---- pipeline advance (R14 scheme) ----
        if (s <= 9) {
            __syncthreads();           // all warps done reading buffer bf
            stage_xq(s + 2, bf);       // refill bf for stage s+2
            stage_w(s + 2, bf);
            cp_commit();
            cp_wait1();                // stage s+1's group complete
            __syncthreads();
        } else if (s == 10) {
            cp_wait0();
            __syncthreads();
        }
    }

    // ---- epilogue: out[b][o][d][h][w] = s*(acc + bias[o]) ----
    const float sb = g_s[b];
    const int h = h0 + wid;
    #pragma unroll
    for (int ni = 0; ni < 4; ni++) {
        const int o0 = ni * 8 + 2 * tig;
        const float bs0 = g_bias[o0];
        const float bs1 = g_bias[o0 + 1];
        float* p0 = out + (((size_t)(b * COUT + o0) * DD + d) * HH_ + h) * WW;
        float* p1 = out + (((size_t)(b * COUT + o0 + 1) * DD + d) * HH_ + h) * WW;
        #pragma unroll
        for (int mi = 0; mi < 4; mi++) {
            const int w = mi * 16 + g;
            p0[w]     = sb * (acc[mi][ni][0] + bs0);
            p1[w]     = sb * (acc[mi][ni][1] + bs1);
            p0[w + 8] = sb * (acc[mi][ni][2] + bs0);
            p1[w + 8] = sb * (acc[mi][ni][3] + bs1);
        }
    }
}

extern "C" void kernel_launch(void* const* d_in, const int* in_sizes, int n_in,
                              void* d_out, int out_size) {
    // x: 16777216, rw: 64, weight: 221184, bias: 256
    const float *x = nullptr, *rw = nullptr, *wt = nullptr, *bi = nullptr;
    for (int i = 0; i < n_in; i++) {
        if (in_sizes[i] == 16777216)     x  = (const float*)d_in[i];
        else if (in_sizes[i] == 221184)  wt = (const float*)d_in[i];
        else if (in_sizes[i] == 256)     bi = (const float*)d_in[i];
        else if (in_sizes[i] == 64)      rw = (const float*)d_in[i];
    }
    float* out = (float*)d_out;

    cudaFuncSetAttribute(conv_kernel,
                         cudaFuncAttributeMaxDynamicSharedMemorySize,
                         SMEM_FLOATS * 4);

    prep_kernel<<<(W_FLOATS + 255) / 256, 256>>>(wt, bi, rw);

    dim3 grid(HH_ / TH, DD, B_);   // (8, 16, 8) = 1024 blocks
    conv_kernel<<<grid, 256, SMEM_FLOATS * 4>>>(x, out);
}